// round 5
// baseline (speedup 1.0000x reference)
#include <cuda_runtime.h>

// Water constraint residuals:
//   x: [B=16, N=200000, D=18] fp32  (first 9 floats per row = 3 particles x xyz)
//   l: [3] fp32 bond lengths
//   out: [B, N, 3] fp32 = |r0-r1|-l0, |r1-r2|-l1, |r2-r0|-l2
//
// One thread per molecule. Row stride 72B (8B aligned) -> 4x LDG.64 + 1x LDG.32,
// all front-batched for MLP. Streaming cache hints (zero reuse, 230MB >> L2).

__global__ __launch_bounds__(256) void water_kernel(
    const float* __restrict__ x,
    const float* __restrict__ l,
    float* __restrict__ out,
    int M)
{
    const float l0 = __ldg(l + 0);
    const float l1 = __ldg(l + 1);
    const float l2 = __ldg(l + 2);

    for (int m = blockIdx.x * blockDim.x + threadIdx.x; m < M;
         m += gridDim.x * blockDim.x)
    {
        const float* row = x + (size_t)m * 18;
        const float2* p = reinterpret_cast<const float2*>(row);

        // Front-batch all loads.
        float2 a0 = __ldcs(p + 0);   // x0 y0
        float2 a1 = __ldcs(p + 1);   // z0 x1
        float2 a2 = __ldcs(p + 2);   // y1 z1
        float2 a3 = __ldcs(p + 3);   // x2 y2
        float  a8 = __ldcs(row + 8); // z2

        // r0 = (a0.x, a0.y, a1.x)
        // r1 = (a1.y, a2.x, a2.y)
        // r2 = (a3.x, a3.y, a8)

        float d0x = a0.x - a1.y;   // r0 - r1
        float d0y = a0.y - a2.x;
        float d0z = a1.x - a2.y;
        float d1x = a1.y - a3.x;   // r1 - r2
        float d1y = a2.x - a3.y;
        float d1z = a2.y - a8;
        float d2x = a3.x - a0.x;   // r2 - r0
        float d2y = a3.y - a0.y;
        float d2z = a8  - a1.x;

        float n0 = sqrtf(fmaf(d0x, d0x, fmaf(d0y, d0y, d0z * d0z)));
        float n1 = sqrtf(fmaf(d1x, d1x, fmaf(d1y, d1y, d1z * d1z)));
        float n2 = sqrtf(fmaf(d2x, d2x, fmaf(d2y, d2y, d2z * d2z)));

        float* o = out + (size_t)m * 3;
        __stcs(o + 0, n0 - l0);
        __stcs(o + 1, n1 - l1);
        __stcs(o + 2, n2 - l2);
    }
}

extern "C" void kernel_launch(void* const* d_in, const int* in_sizes, int n_in,
                              void* d_out, int out_size)
{
    const float* x = (const float*)d_in[0];
    const float* l = (const float*)d_in[1];
    float* out = (float*)d_out;

    int M = in_sizes[0] / 18;  // 16 * 200000 = 3,200,000 molecules

    int block = 256;
    int grid = (M + block - 1) / block;
    water_kernel<<<grid, block>>>(x, l, out, M);
}

// round 7
// speedup vs baseline: 1.0942x; 1.0942x over previous
#include <cuda_runtime.h>

// Water constraint residuals:
//   x: [B=16, N=200000, D=18] fp32  (first 9 floats per row = 3 particles x xyz)
//   l: [3] fp32 bond lengths
//   out: [B, N, 3] fp32 = |r0-r1|-l0, |r1-r2|-l1, |r2-r0|-l2
//
// TWO molecules per thread: a row-pair is 144B and 16B-aligned, so the
// 18 needed floats are covered by 6x LDG.128 at byte offsets
// {0,16,32,64,80,96} — identical DRAM sector footprint to scalar loads
// (8 of 9 sectors per 288B), but 40% fewer load instructions and ~2x
// fewer L1tex wavefronts. Streaming hints: zero reuse, 230MB >> L2.

__global__ __launch_bounds__(256) void water_kernel2(
    const float* __restrict__ x,
    const float* __restrict__ l,
    float* __restrict__ out,
    int P)   // P = number of molecule PAIRS
{
    int t = blockIdx.x * blockDim.x + threadIdx.x;
    if (t >= P) return;

    const float l0 = __ldg(l + 0);
    const float l1 = __ldg(l + 1);
    const float l2 = __ldg(l + 2);

    const float4* p = reinterpret_cast<const float4*>(x + (size_t)t * 36);

    // Front-batch all 6 wide loads.
    float4 q0 = __ldcs(p + 0);  // f0  f1  f2  f3
    float4 q1 = __ldcs(p + 1);  // f4  f5  f6  f7
    float4 q2 = __ldcs(p + 2);  // f8  (f9 f10 f11 unused)
    float4 q3 = __ldcs(p + 4);  // f16 f17 f18 f19  (need f18 f19)
    float4 q4 = __ldcs(p + 5);  // f20 f21 f22 f23
    float4 q5 = __ldcs(p + 6);  // f24 f25 f26 f27  (need f24 f25 f26)

    // ---- molecule A: r0=(q0.x,q0.y,q0.z) r1=(q0.w,q1.x,q1.y) r2=(q1.z,q1.w,q2.x)
    float a0x = q0.x - q0.w;   // r0 - r1
    float a0y = q0.y - q1.x;
    float a0z = q0.z - q1.y;
    float a1x = q0.w - q1.z;   // r1 - r2
    float a1y = q1.x - q1.w;
    float a1z = q1.y - q2.x;
    float a2x = q1.z - q0.x;   // r2 - r0
    float a2y = q1.w - q0.y;
    float a2z = q2.x - q0.z;

    // ---- molecule B: r0=(q3.z,q3.w,q4.x) r1=(q4.y,q4.z,q4.w) r2=(q5.x,q5.y,q5.z)
    float b0x = q3.z - q4.y;
    float b0y = q3.w - q4.z;
    float b0z = q4.x - q4.w;
    float b1x = q4.y - q5.x;
    float b1y = q4.z - q5.y;
    float b1z = q4.w - q5.z;
    float b2x = q5.x - q3.z;
    float b2y = q5.y - q3.w;
    float b2z = q5.z - q4.x;

    float na0 = sqrtf(fmaf(a0x, a0x, fmaf(a0y, a0y, a0z * a0z)));
    float na1 = sqrtf(fmaf(a1x, a1x, fmaf(a1y, a1y, a1z * a1z)));
    float na2 = sqrtf(fmaf(a2x, a2x, fmaf(a2y, a2y, a2z * a2z)));
    float nb0 = sqrtf(fmaf(b0x, b0x, fmaf(b0y, b0y, b0z * b0z)));
    float nb1 = sqrtf(fmaf(b1x, b1x, fmaf(b1y, b1y, b1z * b1z)));
    float nb2 = sqrtf(fmaf(b2x, b2x, fmaf(b2y, b2y, b2z * b2z)));

    // 6 contiguous output floats per thread, 8B-aligned -> 3x STG.64
    float2* o = reinterpret_cast<float2*>(out + (size_t)t * 6);
    __stcs(o + 0, make_float2(na0 - l0, na1 - l1));
    __stcs(o + 1, make_float2(na2 - l2, nb0 - l0));
    __stcs(o + 2, make_float2(nb1 - l1, nb2 - l2));
}

extern "C" void kernel_launch(void* const* d_in, const int* in_sizes, int n_in,
                              void* d_out, int out_size)
{
    const float* x = (const float*)d_in[0];
    const float* l = (const float*)d_in[1];
    float* out = (float*)d_out;

    int M = in_sizes[0] / 18;  // 3,200,000 molecules (even)
    int P = M / 2;             // 1,600,000 pairs

    int block = 256;
    int grid = (P + block - 1) / block;  // 6250
    water_kernel2<<<grid, block>>>(x, l, out, P);
}